// round 15
// baseline (speedup 1.0000x reference)
#include <cuda_runtime.h>
#include <cstdint>

// Problem constants: B=8, N=500000, H=W=512, HALF_CENTOR=true
#define BB    8
#define NPTS  500000
#define HH    512
#define WW    512
#define HW    (HH * WW)          // 262,144 cells per batch
#define NCELL (BB * HW)          // 2,097,152 cells

#define T         256
#define SCAT_BPB  ((NPTS + T - 1) / T)   // 1954 scatter blocks per batch
#define FIN_BPB   ((HW / 4) / T)         // 256 finalize blocks per batch (4 cells/thr)

// Separate scratch arrays; zero sentinel for both (module-load zero init);
// finalize restores zeros after reading -> every call/replay starts clean.
//   g_min[cell] = max over points of mkey = ~enc_f(cost)  (>=1 for any float)
//   g_cnt[cell] = number of points in the cell
__device__ unsigned int g_min[NCELL];   // 8 MB
__device__ unsigned int g_cnt[NCELL];   // 8 MB

// Order-preserving float -> uint (monotone increasing).
__device__ __forceinline__ unsigned int enc_f(float f) {
    unsigned int u = __float_as_uint(f);
    return (u & 0x80000000u) ? ~u : (u | 0x80000000u);
}
__device__ __forceinline__ float dec_f(unsigned int u) {
    return __uint_as_float((u & 0x80000000u) ? (u & 0x7FFFFFFFu) : ~u);
}

// Scatter body: 1 point/thread, unconditional fire-and-forget REDs (proven;
// at the LTS atomic-ALU floor of ~1 op/cyc/slice).
__device__ __forceinline__ void scatter_one(const float2* __restrict__ points,
                                            const float*  __restrict__ costs,
                                            int b, int t) {
    if (t >= NPTS) return;
    int gi = b * NPTS + t;
    float2 p = points[gi];
    int ix = (int)floorf(p.x + 0.5f);
    int iy = (int)floorf(p.y + 0.5f);
    if ((unsigned)ix < (unsigned)WW && (unsigned)iy < (unsigned)HH) {
        int cell = b * HW + iy * WW + ix;
        float c = costs[gi];
        atomicMax(&g_min[cell], ~enc_f(c));  // RED (result unused)
        atomicAdd(&g_cnt[cell], 1u);         // RED
    }
}

// Finalize body: one uint4-group (4 cells), proven 9.4us shape, plain stores.
__device__ __forceinline__ void final_group(float* __restrict__ out_cost,
                                            float* __restrict__ out_mask,
                                            const float* __restrict__ default_cost,
                                            int g) {
    uint4 m = reinterpret_cast<const uint4*>(g_min)[g];
    uint4 c = reinterpret_cast<const uint4*>(g_cnt)[g];

    float d = __ldg(default_cost);
    float4 cost;
    cost.x = c.x ? dec_f(~m.x) : d;
    cost.y = c.y ? dec_f(~m.y) : d;
    cost.z = c.z ? dec_f(~m.z) : d;
    cost.w = c.w ? dec_f(~m.w) : d;
    reinterpret_cast<float4*>(out_cost)[g] = cost;

    if (out_mask) {
        float4 mk = make_float4((float)((int)c.x - 1), (float)((int)c.y - 1),
                                (float)((int)c.z - 1), (float)((int)c.w - 1));
        reinterpret_cast<float4*>(out_mask)[g] = mk;
    }

    // restore zero sentinels (L2-resident; next call starts clean)
    uint4 z = make_uint4(0u, 0u, 0u, 0u);
    reinterpret_cast<uint4*>(g_min)[g] = z;
    reinterpret_cast<uint4*>(g_cnt)[g] = z;
}

// Head: pure scatter of batches [b0, b0+nb).
__global__ void k_scatter(const float2* __restrict__ points,
                          const float*  __restrict__ costs, int b0) {
    int bb = blockIdx.x / SCAT_BPB;
    int t  = (blockIdx.x - bb * SCAT_BPB) * T + threadIdx.x;
    scatter_one(points, costs, b0 + bb, t);
}

// Mix: scatter batches [scat_b0, ...) in blocks [0, nscat) (scheduled first,
// the long pole); finalize groups [fin_g0, ...) in the remaining blocks.
// Finalized batches were scattered in a PREVIOUS launch (fence at boundary).
__global__ void k_mix(const float2* __restrict__ points,
                      const float*  __restrict__ costs,
                      float* __restrict__ out_cost,
                      float* __restrict__ out_mask,
                      const float* __restrict__ default_cost,
                      int scat_b0, int nscat, int fin_g0) {
    if ((int)blockIdx.x < nscat) {
        int bb = blockIdx.x / SCAT_BPB;
        int t  = (blockIdx.x - bb * SCAT_BPB) * T + threadIdx.x;
        scatter_one(points, costs, scat_b0 + bb, t);
    } else {
        int g = (blockIdx.x - nscat) * T + threadIdx.x + fin_g0;
        final_group(out_cost, out_mask, default_cost, g);
    }
}

// Tail: pure finalize of groups [g0, g0 + gridDim.x*T).
__global__ void k_final(float* __restrict__ out_cost,
                        float* __restrict__ out_mask,
                        const float* __restrict__ default_cost, int g0) {
    final_group(out_cost, out_mask, default_cost,
                blockIdx.x * T + threadIdx.x + g0);
}

// ---------------------------------------------------------------------------
// Launcher: staggered 4-launch pipeline (small exposed head/tail).
//   L0: scatter(b0,b1)
//   L1: scatter(b2..b4) || finalize(b0,b1)
//   L2: scatter(b5..b7) || finalize(b2..b4)
//   L3: finalize(b5..b7)
// Inputs: points[B,N,2] f32, costs[B,N] f32, default_cost f32, height i32,
// width i32. Output: [cost | mask] as f32.
// ---------------------------------------------------------------------------
extern "C" void kernel_launch(void* const* d_in, const int* in_sizes, int n_in,
                              void* d_out, int out_size) {
    const float2* points       = (const float2*)d_in[0];
    const float*  costs        = (const float*)d_in[1];
    const float*  default_cost = (const float*)d_in[2];

    float* out_cost = (float*)d_out;
    float* out_mask = (out_size >= 2 * NCELL) ? out_cost + NCELL : nullptr;

    const int GPB = HW / 4;                       // uint4 groups per batch

    // L0: scatter batches 0-1
    k_scatter<<<2 * SCAT_BPB, T>>>(points, costs, 0);

    // L1: scatter batches 2-4  +  finalize batches 0-1
    k_mix<<<3 * SCAT_BPB + 2 * FIN_BPB, T>>>(points, costs, out_cost, out_mask,
                                             default_cost,
                                             /*scat_b0=*/2, /*nscat=*/3 * SCAT_BPB,
                                             /*fin_g0=*/0);

    // L2: scatter batches 5-7  +  finalize batches 2-4
    k_mix<<<3 * SCAT_BPB + 3 * FIN_BPB, T>>>(points, costs, out_cost, out_mask,
                                             default_cost,
                                             /*scat_b0=*/5, /*nscat=*/3 * SCAT_BPB,
                                             /*fin_g0=*/2 * GPB);

    // L3: finalize batches 5-7
    k_final<<<3 * FIN_BPB, T>>>(out_cost, out_mask, default_cost, 5 * GPB);
}